// round 2
// baseline (speedup 1.0000x reference)
#include <cuda_runtime.h>

#define D 128
#define NMAX 50000

// Scratch (no cudaMalloc allowed): scatter-sum accumulator + degree counts.
// 16B alignment required for red.global.add.v4.f32.
__device__ __align__(16) float g_summed[NMAX * D];
__device__ float g_cnt[NMAX];

__device__ __forceinline__ void red_add_v4(float* p, float4 v) {
    asm volatile("red.global.add.v4.f32 [%0], {%1,%2,%3,%4};"
                 :: "l"(p), "f"(v.x), "f"(v.y), "f"(v.z), "f"(v.w) : "memory");
}

__device__ __forceinline__ unsigned long long pack2(float lo, float hi) {
    unsigned long long r;
    asm("mov.b64 %0, {%1,%2};" : "=l"(r) : "f"(lo), "f"(hi));
    return r;
}

__device__ __forceinline__ void fma2(unsigned long long& d,
                                     unsigned long long a,
                                     unsigned long long b) {
    asm("fma.rn.f32x2 %0, %1, %2, %0;" : "+l"(d) : "l"(a), "l"(b));
}

__device__ __forceinline__ float lo32(unsigned long long v) {
    return __uint_as_float((unsigned)(v & 0xFFFFFFFFu));
}
__device__ __forceinline__ float hi32(unsigned long long v) {
    return __uint_as_float((unsigned)(v >> 32));
}

// ---------------------------------------------------------------------------
// K0: zero the accumulators (graph replays; must re-zero every launch).
// ---------------------------------------------------------------------------
__global__ void k_zero(int n) {
    int i = blockIdx.x * blockDim.x + threadIdx.x;
    if (i < n * (D / 4))
        ((float4*)g_summed)[i] = make_float4(0.f, 0.f, 0.f, 0.f);
    if (i < n)
        g_cnt[i] = 0.f;
}

// ---------------------------------------------------------------------------
// K1: one warp per edge. Lane l handles features [4l, 4l+4).
// msg = relu(hidden[src] + ea*We + be); red.v4 into summed[dst]; count dst.
// edge_index is int32 (JAX silently downcasts int64 without x64 mode).
// ---------------------------------------------------------------------------
__global__ void k_scatter(const float* __restrict__ hidden,
                          const int* __restrict__ ei,
                          const float* __restrict__ ea,
                          const float* __restrict__ We,
                          const float* __restrict__ be,
                          int E, int N) {
    int gw = (blockIdx.x * blockDim.x + threadIdx.x) >> 5;
    int lane = threadIdx.x & 31;
    if (gw >= E) return;

    int src = __ldg(ei + gw);
    int dst = __ldg(ei + E + gw);
    // Defensive clamp: valid data is unchanged; bad data -> wrong answer, not a crash.
    src = min(max(src, 0), N - 1);
    dst = min(max(dst, 0), N - 1);
    float a = __ldg(ea + gw);

    float4 w = __ldg((const float4*)We + lane);
    float4 b = __ldg((const float4*)be + lane);
    float4 h = __ldg((const float4*)(hidden + (size_t)src * D) + lane);

    float4 m;
    m.x = fmaxf(h.x + fmaf(a, w.x, b.x), 0.f);
    m.y = fmaxf(h.y + fmaf(a, w.y, b.y), 0.f);
    m.z = fmaxf(h.z + fmaf(a, w.z, b.z), 0.f);
    m.w = fmaxf(h.w + fmaf(a, w.w, b.w), 0.f);

    red_add_v4(g_summed + (size_t)dst * D + lane * 4, m);
    if (lane == 0) atomicAdd(g_cnt + dst, 1.0f);
}

// ---------------------------------------------------------------------------
// K2: fused node update + 2-layer MLP (f32x2 packed FFMA).
//   h0 = (1+eps)*hidden + summed/max(cnt,1)
//   h1 = relu(h0 @ W1 + b1); out = h1 @ W2 + b2
// Block: 256 threads, 64 nodes. Warp w owns rows w*8..w*8+7;
// lane l owns cols 4l..4l+3 (2 f32x2 accumulators per row).
// ---------------------------------------------------------------------------
__global__ __launch_bounds__(256, 3) void k_mlp(
    const float* __restrict__ hidden,
    const float* __restrict__ W1, const float* __restrict__ b1,
    const float* __restrict__ W2, const float* __restrict__ b2,
    const float* __restrict__ eps,
    float* __restrict__ out, int N) {

    __shared__ float As[64][132];   // h0 / h1 tile (padded rows, 16B-aligned)
    __shared__ float Ws[16][128];   // weight k-panel

    int tid = threadIdx.x;
    int w = tid >> 5;
    int l = tid & 31;
    int node0 = blockIdx.x * 64;
    float ep1 = 1.0f + __ldg(eps);

    // Prologue: build h0 tile.
    for (int i = tid; i < 64 * 32; i += 256) {
        int m = i >> 5, c = i & 31;
        int g = node0 + m;
        float4 v = make_float4(0.f, 0.f, 0.f, 0.f);
        if (g < N) {
            float4 h = __ldg((const float4*)(hidden + (size_t)g * D) + c);
            float4 s = ((const float4*)(g_summed + (size_t)g * D))[c];
            float ic = 1.0f / fmaxf(g_cnt[g], 1.0f);
            v.x = fmaf(ep1, h.x, s.x * ic);
            v.y = fmaf(ep1, h.y, s.y * ic);
            v.z = fmaf(ep1, h.z, s.z * ic);
            v.w = fmaf(ep1, h.w, s.w * ic);
        }
        ((float4*)&As[m][0])[c] = v;
    }
    // (first __syncthreads inside the k-panel loop orders these writes)

    unsigned long long acc[8][2];
    const float* Wg = W1;

    #pragma unroll 1
    for (int layer = 0; layer < 2; ++layer) {
        #pragma unroll
        for (int i = 0; i < 8; ++i) { acc[i][0] = 0ull; acc[i][1] = 0ull; }

        for (int kk = 0; kk < D; kk += 16) {
            // Stage 16x128 weight panel.
            for (int i = tid; i < 16 * 32; i += 256) {
                int r = i >> 5, c = i & 31;
                ((float4*)&Ws[r][0])[c] =
                    __ldg((const float4*)(Wg + (size_t)(kk + r) * D) + c);
            }
            __syncthreads();

            #pragma unroll
            for (int k2 = 0; k2 < 16; k2 += 2) {
                ulonglong2 wv0 = ((const ulonglong2*)&Ws[k2][0])[l];
                ulonglong2 wv1 = ((const ulonglong2*)&Ws[k2 + 1][0])[l];
                #pragma unroll
                for (int i = 0; i < 8; ++i) {
                    float2 a = *(const float2*)&As[w * 8 + i][kk + k2];
                    unsigned long long a0 = pack2(a.x, a.x);
                    unsigned long long a1 = pack2(a.y, a.y);
                    fma2(acc[i][0], a0, wv0.x);
                    fma2(acc[i][1], a0, wv0.y);
                    fma2(acc[i][0], a1, wv1.x);
                    fma2(acc[i][1], a1, wv1.y);
                }
            }
            __syncthreads();
        }

        if (layer == 0) {
            float4 bias = __ldg((const float4*)b1 + l);
            #pragma unroll
            for (int i = 0; i < 8; ++i) {
                float4 v;
                v.x = fmaxf(lo32(acc[i][0]) + bias.x, 0.f);
                v.y = fmaxf(hi32(acc[i][0]) + bias.y, 0.f);
                v.z = fmaxf(lo32(acc[i][1]) + bias.z, 0.f);
                v.w = fmaxf(hi32(acc[i][1]) + bias.w, 0.f);
                ((float4*)&As[w * 8 + i][0])[l] = v;   // h1 into tile
            }
            Wg = W2;
            // next panel-load's __syncthreads orders these writes vs reads
        } else {
            float4 bias = __ldg((const float4*)b2 + l);
            #pragma unroll
            for (int i = 0; i < 8; ++i) {
                int g = node0 + w * 8 + i;
                if (g < N) {
                    float4 v;
                    v.x = lo32(acc[i][0]) + bias.x;
                    v.y = hi32(acc[i][0]) + bias.y;
                    v.z = lo32(acc[i][1]) + bias.z;
                    v.w = hi32(acc[i][1]) + bias.w;
                    ((float4*)(out + (size_t)g * D))[l] = v;
                }
            }
        }
    }
}

// ---------------------------------------------------------------------------
extern "C" void kernel_launch(void* const* d_in, const int* in_sizes, int n_in,
                              void* d_out, int out_size) {
    const float* hidden = (const float*)d_in[0];
    const int*   ei     = (const int*)d_in[1];     // int32! (JAX x64 disabled)
    const float* ea     = (const float*)d_in[2];
    const float* We     = (const float*)d_in[3];
    const float* be     = (const float*)d_in[4];
    const float* W1     = (const float*)d_in[5];
    const float* b1     = (const float*)d_in[6];
    const float* W2     = (const float*)d_in[7];
    const float* b2     = (const float*)d_in[8];
    const float* eps    = (const float*)d_in[9];
    float* out = (float*)d_out;

    int N = in_sizes[0] / D;       // 50000
    int E = in_sizes[2];           // 800000 (edge_attr is [E,1])

    int zt = N * 32;               // float4 count for summed (covers cnt too)
    k_zero<<<(zt + 255) / 256, 256>>>(N);

    long long sthreads = (long long)E * 32;
    k_scatter<<<(int)((sthreads + 255) / 256), 256>>>(hidden, ei, ea, We, be, E, N);

    k_mlp<<<(N + 63) / 64, 256>>>(hidden, W1, b1, W2, b2, eps, out, N);
}

// round 4
// speedup vs baseline: 1.0326x; 1.0326x over previous
#include <cuda_runtime.h>

#define D 128
#define NMAX 50000
#define EPW 8   // edges per warp in the scatter kernel

// Scratch (no cudaMalloc allowed). Starts zero-initialized; k_mlp re-zeroes
// after consuming, so every graph replay sees zeros. 16B align for red.v4.
__device__ __align__(16) float g_summed[NMAX * D];
__device__ float g_cnt[NMAX];

__device__ __forceinline__ void red_add_v4(float* p, float4 v) {
    asm volatile("red.global.add.v4.f32 [%0], {%1,%2,%3,%4};"
                 :: "l"(p), "f"(v.x), "f"(v.y), "f"(v.z), "f"(v.w) : "memory");
}

__device__ __forceinline__ unsigned long long pack2(float lo, float hi) {
    unsigned long long r;
    asm("mov.b64 %0, {%1,%2};" : "=l"(r) : "f"(lo), "f"(hi));
    return r;
}

__device__ __forceinline__ void fma2(unsigned long long& d,
                                     unsigned long long a,
                                     unsigned long long b) {
    asm("fma.rn.f32x2 %0, %1, %2, %0;" : "+l"(d) : "l"(a), "l"(b));
}

__device__ __forceinline__ float lo32(unsigned long long v) {
    return __uint_as_float((unsigned)(v & 0xFFFFFFFFu));
}
__device__ __forceinline__ float hi32(unsigned long long v) {
    return __uint_as_float((unsigned)(v >> 32));
}

// ---------------------------------------------------------------------------
// K1: each warp handles EPW edges. Lane l owns features [4l, 4l+4).
// Phase 1 (unrolled): gather hidden[src], build msg -> registers (batched LDGs).
// Phase 2: fire REDs. We/be hoisted to registers once per warp.
// ---------------------------------------------------------------------------
__global__ __launch_bounds__(256) void k_scatter(
    const float* __restrict__ hidden,
    const int* __restrict__ ei,       // int32 (JAX x64 disabled)
    const float* __restrict__ ea,
    const float* __restrict__ We,
    const float* __restrict__ be,
    int E, int N) {

    int gw = (blockIdx.x * blockDim.x + threadIdx.x) >> 5;  // global warp id
    int lane = threadIdx.x & 31;
    int e0 = gw * EPW;
    if (e0 >= E) return;

    float4 w = __ldg((const float4*)We + lane);
    float4 b = __ldg((const float4*)be + lane);

    int dst[EPW];
    float4 m[EPW];
    bool valid[EPW];

    #pragma unroll
    for (int e = 0; e < EPW; ++e) {
        int idx = e0 + e;
        valid[e] = (idx < E);
        int src = 0;
        dst[e] = 0;
        float a = 0.f;
        if (valid[e]) {
            src = __ldg(ei + idx);
            dst[e] = __ldg(ei + E + idx);
            a = __ldg(ea + idx);
            src = min(max(src, 0), N - 1);
            dst[e] = min(max(dst[e], 0), N - 1);
        }
        float4 h = __ldg((const float4*)(hidden + (size_t)src * D) + lane);
        m[e].x = fmaxf(h.x + fmaf(a, w.x, b.x), 0.f);
        m[e].y = fmaxf(h.y + fmaf(a, w.y, b.y), 0.f);
        m[e].z = fmaxf(h.z + fmaf(a, w.z, b.z), 0.f);
        m[e].w = fmaxf(h.w + fmaf(a, w.w, b.w), 0.f);
    }

    #pragma unroll
    for (int e = 0; e < EPW; ++e) {
        if (valid[e]) {
            red_add_v4(g_summed + (size_t)dst[e] * D + lane * 4, m[e]);
            if (lane == 0) atomicAdd(g_cnt + dst[e], 1.0f);
        }
    }
}

// ---------------------------------------------------------------------------
// K2: fused node update + 2-layer MLP (f32x2 packed FFMA), and re-zeroes the
// accumulators it consumed (replaces a separate zero kernel).
//   h0 = (1+eps)*hidden + summed/max(cnt,1)
//   h1 = relu(h0 @ W1 + b1); out = h1 @ W2 + b2
// Block: 256 threads, 64 nodes. Warp w owns rows w*8..w*8+7;
// lane l owns cols 4l..4l+3 (2 f32x2 accumulators per row).
// ---------------------------------------------------------------------------
__global__ __launch_bounds__(256, 3) void k_mlp(
    const float* __restrict__ hidden,
    const float* __restrict__ W1, const float* __restrict__ b1,
    const float* __restrict__ W2, const float* __restrict__ b2,
    const float* __restrict__ eps,
    float* __restrict__ out, int N) {

    __shared__ float As[64][132];   // h0 / h1 tile (padded rows, 16B-aligned)
    __shared__ float Ws[16][128];   // weight k-panel

    int tid = threadIdx.x;
    int w = tid >> 5;
    int l = tid & 31;
    int node0 = blockIdx.x * 64;
    float ep1 = 1.0f + __ldg(eps);

    // Prologue: build h0 tile. g_summed is reset by the same thread that read
    // each element (race-free). g_cnt is reset only AFTER the barrier below:
    // its readers span other warps (this was the R3 race).
    const float4 z4 = make_float4(0.f, 0.f, 0.f, 0.f);
    for (int i = tid; i < 64 * 32; i += 256) {
        int m = i >> 5, c = i & 31;
        int g = node0 + m;
        float4 v = z4;
        if (g < N) {
            float4 h = __ldg((const float4*)(hidden + (size_t)g * D) + c);
            float4 s = ((const float4*)(g_summed + (size_t)g * D))[c];
            float ic = 1.0f / fmaxf(g_cnt[g], 1.0f);
            v.x = fmaf(ep1, h.x, s.x * ic);
            v.y = fmaf(ep1, h.y, s.y * ic);
            v.z = fmaf(ep1, h.z, s.z * ic);
            v.w = fmaf(ep1, h.w, s.w * ic);
            ((float4*)(g_summed + (size_t)g * D))[c] = z4;  // reset for next replay
        }
        ((float4*)&As[m][0])[c] = v;
    }
    __syncthreads();   // all g_cnt reads (and As writes) complete before reset
    if (tid < 64 && node0 + tid < N) g_cnt[node0 + tid] = 0.f;

    unsigned long long acc[8][2];
    const float* Wg = W1;

    #pragma unroll 1
    for (int layer = 0; layer < 2; ++layer) {
        #pragma unroll
        for (int i = 0; i < 8; ++i) { acc[i][0] = 0ull; acc[i][1] = 0ull; }

        for (int kk = 0; kk < D; kk += 16) {
            // Stage 16x128 weight panel.
            for (int i = tid; i < 16 * 32; i += 256) {
                int r = i >> 5, c = i & 31;
                ((float4*)&Ws[r][0])[c] =
                    __ldg((const float4*)(Wg + (size_t)(kk + r) * D) + c);
            }
            __syncthreads();

            #pragma unroll
            for (int k2 = 0; k2 < 16; k2 += 2) {
                ulonglong2 wv0 = ((const ulonglong2*)&Ws[k2][0])[l];
                ulonglong2 wv1 = ((const ulonglong2*)&Ws[k2 + 1][0])[l];
                #pragma unroll
                for (int i = 0; i < 8; ++i) {
                    float2 a = *(const float2*)&As[w * 8 + i][kk + k2];
                    unsigned long long a0 = pack2(a.x, a.x);
                    unsigned long long a1 = pack2(a.y, a.y);
                    fma2(acc[i][0], a0, wv0.x);
                    fma2(acc[i][1], a0, wv0.y);
                    fma2(acc[i][0], a1, wv1.x);
                    fma2(acc[i][1], a1, wv1.y);
                }
            }
            __syncthreads();
        }

        if (layer == 0) {
            float4 bias = __ldg((const float4*)b1 + l);
            #pragma unroll
            for (int i = 0; i < 8; ++i) {
                float4 v;
                v.x = fmaxf(lo32(acc[i][0]) + bias.x, 0.f);
                v.y = fmaxf(hi32(acc[i][0]) + bias.y, 0.f);
                v.z = fmaxf(lo32(acc[i][1]) + bias.z, 0.f);
                v.w = fmaxf(hi32(acc[i][1]) + bias.w, 0.f);
                ((float4*)&As[w * 8 + i][0])[l] = v;   // h1 into tile
            }
            Wg = W2;
            // next panel-load's __syncthreads orders these writes vs reads
        } else {
            float4 bias = __ldg((const float4*)b2 + l);
            #pragma unroll
            for (int i = 0; i < 8; ++i) {
                int g = node0 + w * 8 + i;
                if (g < N) {
                    float4 v;
                    v.x = lo32(acc[i][0]) + bias.x;
                    v.y = hi32(acc[i][0]) + bias.y;
                    v.z = lo32(acc[i][1]) + bias.z;
                    v.w = hi32(acc[i][1]) + bias.w;
                    ((float4*)(out + (size_t)g * D))[l] = v;
                }
            }
        }
    }
}

// ---------------------------------------------------------------------------
extern "C" void kernel_launch(void* const* d_in, const int* in_sizes, int n_in,
                              void* d_out, int out_size) {
    const float* hidden = (const float*)d_in[0];
    const int*   ei     = (const int*)d_in[1];     // int32! (JAX x64 disabled)
    const float* ea     = (const float*)d_in[2];
    const float* We     = (const float*)d_in[3];
    const float* be     = (const float*)d_in[4];
    const float* W1     = (const float*)d_in[5];
    const float* b1     = (const float*)d_in[6];
    const float* W2     = (const float*)d_in[7];
    const float* b2     = (const float*)d_in[8];
    const float* eps    = (const float*)d_in[9];
    float* out = (float*)d_out;

    int N = in_sizes[0] / D;       // 50000
    int E = in_sizes[2];           // 800000 (edge_attr is [E,1])

    // 8 warps/block, EPW edges per warp -> 64 edges per block.
    int nwarps = (E + EPW - 1) / EPW;
    int nblocks = (nwarps + 7) / 8;
    k_scatter<<<nblocks, 256>>>(hidden, ei, ea, We, be, E, N);

    k_mlp<<<(N + 63) / 64, 256>>>(hidden, W1, b1, W2, b2, eps, out, N);
}

// round 8
// speedup vs baseline: 1.2295x; 1.1906x over previous
#include <cuda_runtime.h>
#include <cuda_bf16.h>
#include <cstdint>

#define D 128
#define NMAX 50000
#define EPW 8
#define PITCH 272                 // bytes per bf16-tile row (136 bf16, padded)
#define TILE_B (128 * PITCH)      // 34816 bytes per 128x128 bf16 tile

// ---------------------------------------------------------------------------
// Global scratch (no cudaMalloc allowed).
// ---------------------------------------------------------------------------
__device__ __align__(16) float g_summed[NMAX * D];
__device__ float g_cnt[NMAX];
// Preformatted transposed weights Bt[n][k]: B1hi | B1lo | B2hi | B2lo.
__device__ __align__(16) unsigned char g_Bt[4 * TILE_B];

// ---------------------------------------------------------------------------
// Helpers
// ---------------------------------------------------------------------------
__device__ __forceinline__ void red_add_v4(float* p, float4 v) {
    asm volatile("red.global.add.v4.f32 [%0], {%1,%2,%3,%4};"
                 :: "l"(p), "f"(v.x), "f"(v.y), "f"(v.z), "f"(v.w) : "memory");
}

__device__ __forceinline__ uint32_t bf2pack(float a, float b) {
    __nv_bfloat162 t = __floats2bfloat162_rn(a, b);
    return *(uint32_t*)&t;        // a -> low 16 bits
}

__device__ __forceinline__ void ldsm_x4(uint32_t* r, uint32_t addr) {
    asm volatile("ldmatrix.sync.aligned.m8n8.x4.shared.b16 {%0,%1,%2,%3}, [%4];"
                 : "=r"(r[0]), "=r"(r[1]), "=r"(r[2]), "=r"(r[3]) : "r"(addr));
}

__device__ __forceinline__ void mma_bf16(float* c, const uint32_t* a,
                                         const uint32_t* b) {
    asm volatile("mma.sync.aligned.m16n8k16.row.col.f32.bf16.bf16.f32 "
                 "{%0,%1,%2,%3}, {%4,%5,%6,%7}, {%8,%9}, {%0,%1,%2,%3};"
                 : "+f"(c[0]), "+f"(c[1]), "+f"(c[2]), "+f"(c[3])
                 : "r"(a[0]), "r"(a[1]), "r"(a[2]), "r"(a[3]),
                   "r"(b[0]), "r"(b[1]));
}

// ---------------------------------------------------------------------------
// K_prep: W[k][n] row-major -> Bt[n][k] bf16 hi/lo at PITCH-padded rows.
// ---------------------------------------------------------------------------
__global__ void k_prep(const float* __restrict__ W1, const float* __restrict__ W2) {
    int idx = blockIdx.x * blockDim.x + threadIdx.x;
    if (idx >= 128 * 128) return;
    int k = idx >> 7, n = idx & 127;
    uint32_t off = (uint32_t)n * PITCH + (uint32_t)k * 2;

    float x1 = __ldg(W1 + idx);
    __nv_bfloat16 h1 = __float2bfloat16_rn(x1);
    *(__nv_bfloat16*)(g_Bt + off)              = h1;
    *(__nv_bfloat16*)(g_Bt + TILE_B + off)     = __float2bfloat16_rn(x1 - __bfloat162float(h1));

    float x2 = __ldg(W2 + idx);
    __nv_bfloat16 h2 = __float2bfloat16_rn(x2);
    *(__nv_bfloat16*)(g_Bt + 2 * TILE_B + off) = h2;
    *(__nv_bfloat16*)(g_Bt + 3 * TILE_B + off) = __float2bfloat16_rn(x2 - __bfloat162float(h2));
}

// ---------------------------------------------------------------------------
// K1: scatter (unchanged from the 180.5us pass). EPW edges per warp.
// ---------------------------------------------------------------------------
__global__ __launch_bounds__(256) void k_scatter(
    const float* __restrict__ hidden, const int* __restrict__ ei,
    const float* __restrict__ ea, const float* __restrict__ We,
    const float* __restrict__ be, int E, int N) {

    int gw = (blockIdx.x * blockDim.x + threadIdx.x) >> 5;
    int lane = threadIdx.x & 31;
    int e0 = gw * EPW;
    if (e0 >= E) return;

    float4 w = __ldg((const float4*)We + lane);
    float4 b = __ldg((const float4*)be + lane);

    int dst[EPW]; float4 m[EPW]; bool valid[EPW];

    #pragma unroll
    for (int e = 0; e < EPW; ++e) {
        int idx = e0 + e;
        valid[e] = (idx < E);
        int src = 0; dst[e] = 0; float a = 0.f;
        if (valid[e]) {
            src = __ldg(ei + idx);
            dst[e] = __ldg(ei + E + idx);
            a = __ldg(ea + idx);
            src = min(max(src, 0), N - 1);
            dst[e] = min(max(dst[e], 0), N - 1);
        }
        float4 h = __ldg((const float4*)(hidden + (size_t)src * D) + lane);
        m[e].x = fmaxf(h.x + fmaf(a, w.x, b.x), 0.f);
        m[e].y = fmaxf(h.y + fmaf(a, w.y, b.y), 0.f);
        m[e].z = fmaxf(h.z + fmaf(a, w.z, b.z), 0.f);
        m[e].w = fmaxf(h.w + fmaf(a, w.w, b.w), 0.f);
    }
    #pragma unroll
    for (int e = 0; e < EPW; ++e) {
        if (valid[e]) {
            red_add_v4(g_summed + (size_t)dst[e] * D + lane * 4, m[e]);
            if (lane == 0) atomicAdd(g_cnt + dst[e], 1.0f);
        }
    }
}

// ---------------------------------------------------------------------------
// K2: MLP via warp-level mma.sync (bf16 3-pass split, fp32 accum).
// Block: 128 nodes, 256 threads (8 warps = 4 Mx2 N). Smem:
//   Ah | Al | Bh | Bl, each 34816 B (PITCH-padded 128x128 bf16).
// ---------------------------------------------------------------------------
__global__ __launch_bounds__(256) void k_mlp(
    const float* __restrict__ hidden,
    const float* __restrict__ b1, const float* __restrict__ b2,
    const float* __restrict__ eps,
    float* __restrict__ out, int N) {

    extern __shared__ unsigned char sm[];
    unsigned char* smAh = sm;
    unsigned char* smAl = sm + TILE_B;
    unsigned char* smBh = sm + 2 * TILE_B;

    uint32_t sAh = (uint32_t)__cvta_generic_to_shared(smAh);
    uint32_t sAl = sAh + TILE_B;
    uint32_t sBh = sAh + 2 * TILE_B;
    uint32_t sBl = sAh + 3 * TILE_B;

    int tid = threadIdx.x;
    int w = tid >> 5;
    int lane = tid & 31;
    int warp_m = w & 3;          // 32-row M tile
    int warp_n = w >> 2;         // 64-col N tile
    int node0 = blockIdx.x * 128;
    float ep1 = 1.0f + __ldg(eps);

    // Copy layer-1 B tiles (hi|lo contiguous in g_Bt).
    for (int i = tid; i < 2 * TILE_B / 16; i += 256)
        ((uint4*)smBh)[i] = ((const uint4*)g_Bt)[i];

    // Build A tile: h0 = (1+eps)*hidden + summed/max(cnt,1); split hi/lo.
    const float4 z4 = make_float4(0.f, 0.f, 0.f, 0.f);
    for (int i = tid; i < 2048; i += 256) {
        int row = i >> 4;
        int kc = (i & 15) << 3;
        int g = node0 + row;
        float h0[8];
        if (g < N) {
            const float4* hp = (const float4*)(hidden + (size_t)g * D) + (kc >> 2);
            float4* sp = (float4*)(g_summed + (size_t)g * D) + (kc >> 2);
            float4 ha = __ldg(hp), hb = __ldg(hp + 1);
            float4 sa = sp[0],     sb = sp[1];
            float ic = 1.0f / fmaxf(g_cnt[g], 1.0f);
            h0[0] = fmaf(ep1, ha.x, sa.x * ic); h0[1] = fmaf(ep1, ha.y, sa.y * ic);
            h0[2] = fmaf(ep1, ha.z, sa.z * ic); h0[3] = fmaf(ep1, ha.w, sa.w * ic);
            h0[4] = fmaf(ep1, hb.x, sb.x * ic); h0[5] = fmaf(ep1, hb.y, sb.y * ic);
            h0[6] = fmaf(ep1, hb.z, sb.z * ic); h0[7] = fmaf(ep1, hb.w, sb.w * ic);
            sp[0] = z4; sp[1] = z4;                 // reset for next replay
        } else {
            #pragma unroll
            for (int j = 0; j < 8; ++j) h0[j] = 0.f;
        }
        uint4 hw, lw;
        float r[8];
        #pragma unroll
        for (int j = 0; j < 8; ++j) {
            __nv_bfloat16 hb16 = __float2bfloat16_rn(h0[j]);
            r[j] = h0[j] - __bfloat162float(hb16);
        }
        hw.x = bf2pack(h0[0], h0[1]); hw.y = bf2pack(h0[2], h0[3]);
        hw.z = bf2pack(h0[4], h0[5]); hw.w = bf2pack(h0[6], h0[7]);
        lw.x = bf2pack(r[0], r[1]);   lw.y = bf2pack(r[2], r[3]);
        lw.z = bf2pack(r[4], r[5]);   lw.w = bf2pack(r[6], r[7]);
        uint32_t off = (uint32_t)row * PITCH + (uint32_t)kc * 2;
        *(uint4*)(smAh + off)          = hw;
        *(uint4*)(smAh + TILE_B + off) = lw;
    }
    __syncthreads();                               // g_cnt reads + tiles done
    if (tid < 128 && node0 + tid < N) g_cnt[node0 + tid] = 0.f;

    // Per-thread ldmatrix address components.
    uint32_t rowA  = (uint32_t)(warp_m * 32 + (lane & 15));
    uint32_t kselA = (uint32_t)((lane >> 4) * 16);          // bytes
    uint32_t nB    = (uint32_t)(warp_n * 64 + ((lane >> 4) & 1) * 8 + (lane & 7));
    uint32_t kselB = (uint32_t)(((lane >> 3) & 1) * 16);    // bytes

    int quad = lane >> 2, tq = lane & 3;
    float acc[2][8][4];

    #pragma unroll 1
    for (int layer = 0; layer < 2; ++layer) {
        #pragma unroll
        for (int mt = 0; mt < 2; ++mt)
            #pragma unroll
            for (int nt = 0; nt < 8; ++nt)
                #pragma unroll
                for (int q = 0; q < 4; ++q) acc[mt][nt][q] = 0.f;

        // 3 passes: (Ah,Bh), (Ah,Bl), (Al,Bh)
        #pragma unroll 1
        for (int pass = 0; pass < 3; ++pass) {
            uint32_t Ab = (pass == 2) ? sAl : sAh;
            uint32_t Bb = (pass == 1) ? sBl : sBh;
            uint32_t aAddr = Ab + rowA * PITCH + kselA;
            uint32_t bAddr = Bb + nB * PITCH + kselB;
            #pragma unroll
            for (int k16 = 0; k16 < 8; ++k16) {
                uint32_t a0[4], a1[4], bf[4][4];
                ldsm_x4(a0, aAddr + k16 * 32);
                ldsm_x4(a1, aAddr + 16 * PITCH + k16 * 32);
                #pragma unroll
                for (int p = 0; p < 4; ++p)
                    ldsm_x4(bf[p], bAddr + p * 16 * PITCH + k16 * 32);
                #pragma unroll
                for (int p = 0; p < 4; ++p) {
                    mma_bf16(acc[0][2 * p],     a0, &bf[p][0]);
                    mma_bf16(acc[0][2 * p + 1], a0, &bf[p][2]);
                    mma_bf16(acc[1][2 * p],     a1, &bf[p][0]);
                    mma_bf16(acc[1][2 * p + 1], a1, &bf[p][2]);
                }
            }
        }
        __syncthreads();   // everyone done reading A/B before overwrite

        if (layer == 0) {
            // Copy layer-2 B tiles.
            for (int i = tid; i < 2 * TILE_B / 16; i += 256)
                ((uint4*)smBh)[i] = ((const uint4*)(g_Bt + 2 * TILE_B))[i];
            // Epilogue 1: bias + relu, re-split into A tile.
            #pragma unroll
            for (int mt = 0; mt < 2; ++mt) {
                int r0 = warp_m * 32 + mt * 16 + quad;
                #pragma unroll
                for (int nt = 0; nt < 8; ++nt) {
                    int col = warp_n * 64 + nt * 8 + tq * 2;
                    float2 bb = __ldg((const float2*)b1 + (col >> 1));
                    float v0 = fmaxf(acc[mt][nt][0] + bb.x, 0.f);
                    float v1 = fmaxf(acc[mt][nt][1] + bb.y, 0.f);
                    float v2 = fmaxf(acc[mt][nt][2] + bb.x, 0.f);
                    float v3 = fmaxf(acc[mt][nt][3] + bb.y, 0.f);
                    __nv_bfloat16 h0 = __float2bfloat16_rn(v0);
                    __nv_bfloat16 h1 = __float2bfloat16_rn(v1);
                    __nv_bfloat16 h2 = __float2bfloat16_rn(v2);
                    __nv_bfloat16 h3 = __float2bfloat16_rn(v3);
                    uint32_t offA = (uint32_t)r0 * PITCH + (uint32_t)col * 2;
                    uint32_t offB = offA + 8 * PITCH;
                    *(uint32_t*)(smAh + offA) = bf2pack(v0, v1);
                    *(uint32_t*)(smAh + offB) = bf2pack(v2, v3);
                    *(uint32_t*)(smAl + offA) =
                        bf2pack(v0 - __bfloat162float(h0), v1 - __bfloat162float(h1));
                    *(uint32_t*)(smAl + offB) =
                        bf2pack(v2 - __bfloat162float(h2), v3 - __bfloat162float(h3));
                }
            }
            __syncthreads();
        } else {
            // Epilogue 2: out = D + b2.
            #pragma unroll
            for (int mt = 0; mt < 2; ++mt) {
                int r0 = node0 + warp_m * 32 + mt * 16 + quad;
                #pragma unroll
                for (int nt = 0; nt < 8; ++nt) {
                    int col = warp_n * 64 + nt * 8 + tq * 2;
                    float2 bb = __ldg((const float2*)b2 + (col >> 1));
                    if (r0 < N) {
                        float2 v; v.x = acc[mt][nt][0] + bb.x;
                                  v.y = acc[mt][nt][1] + bb.y;
                        *(float2*)(out + (size_t)r0 * D + col) = v;
                    }
                    if (r0 + 8 < N) {
                        float2 v; v.x = acc[mt][nt][2] + bb.x;
                                  v.y = acc[mt][nt][3] + bb.y;
                        *(float2*)(out + (size_t)(r0 + 8) * D + col) = v;
                    }
                }
            }
        }
    }
}

// ---------------------------------------------------------------------------
extern "C" void kernel_launch(void* const* d_in, const int* in_sizes, int n_in,
                              void* d_out, int out_size) {
    const float* hidden = (const float*)d_in[0];
    const int*   ei     = (const int*)d_in[1];     // int32 (JAX x64 disabled)
    const float* ea     = (const float*)d_in[2];
    const float* We     = (const float*)d_in[3];
    const float* be     = (const float*)d_in[4];
    const float* W1     = (const float*)d_in[5];
    const float* b1     = (const float*)d_in[6];
    const float* W2     = (const float*)d_in[7];
    const float* b2     = (const float*)d_in[8];
    const float* eps    = (const float*)d_in[9];
    float* out = (float*)d_out;

    int N = in_sizes[0] / D;       // 50000
    int E = in_sizes[2];           // 800000

    const int DSMEM = 4 * TILE_B;  // 139264 B
    cudaFuncSetAttribute(k_mlp, cudaFuncAttributeMaxDynamicSharedMemorySize, DSMEM);

    k_prep<<<64, 256>>>(W1, W2);

    int nwarps = (E + EPW - 1) / EPW;
    k_scatter<<<(nwarps + 7) / 8, 256>>>(hidden, ei, ea, We, be, E, N);

    k_mlp<<<(N + 127) / 128, 256, DSMEM>>>(hidden, b1, b2, eps, out, N);
}